// round 17
// baseline (speedup 1.0000x reference)
#include <cuda_runtime.h>
#include <cuda_bf16.h>
#include <cuda_fp16.h>
#include <cstdint>
#include <cstddef>

// Problem constants (fixed by setup_inputs: BS=8, L=2048, D=2048, CACHE=64)
#define BSQ   8
#define LSEQ  2048
#define TOK   16384          // BS*L
#define ROWS  16392          // TOK + BS (padded buffer rows)
#define DDIM  2048
#define H1    1024           // conv1 output width
#define K2    2048           // GEMM2 K after Z-concat
#define N2P   2048           // GEMM2 N after fold

// ---------------------------------------------------------------------------
// Device-global scratch (allocation-free path)
// ---------------------------------------------------------------------------
__device__ __half g_XT1[(size_t)ROWS * DDIM];
__device__ __half g_Z[(size_t)TOK * K2];         // Z = [XT2[p], XT2[p+1]]
__device__ __half g_W1t[(size_t)DDIM * DDIM];    // W1^T fp16 [N][K]
__device__ __half g_W2p[(size_t)N2P * K2];       // W2'^T fp16 [N][K]
__device__ __half g_C1[(size_t)ROWS * DDIM];     // fp16 conv1 GEMM output
__device__ __half g_O3[(size_t)TOK * N2P];       // fp16 o3 = C2 + b2 + inputs

// ---------------------------------------------------------------------------
// helpers
// ---------------------------------------------------------------------------
__device__ __forceinline__ uint32_t smem_u32(const void* p) {
    uint32_t a;
    asm("{ .reg .u64 t; cvta.to.shared.u64 t, %1; cvt.u32.u64 %0, t; }"
        : "=r"(a) : "l"(p));
    return a;
}
__device__ __forceinline__ void cp_async16(uint32_t dst, const void* src, uint32_t bytes) {
    asm volatile("cp.async.cg.shared.global [%0], [%1], 16, %2;"
                 :: "r"(dst), "l"(src), "r"(bytes) : "memory");
}
__device__ __forceinline__ void ldsm_x4(uint32_t& r0, uint32_t& r1,
                                        uint32_t& r2, uint32_t& r3, uint32_t addr) {
    asm volatile("ldmatrix.sync.aligned.m8n8.x4.shared.b16 {%0,%1,%2,%3}, [%4];"
                 : "=r"(r0), "=r"(r1), "=r"(r2), "=r"(r3) : "r"(addr));
}
__device__ __forceinline__ void mma_f16(float& c0, float& c1, float& c2, float& c3,
                                        uint32_t a0, uint32_t a1, uint32_t a2, uint32_t a3,
                                        uint32_t b0, uint32_t b1) {
    asm volatile(
        "mma.sync.aligned.m16n8k16.row.col.f32.f16.f16.f32 "
        "{%0,%1,%2,%3}, {%4,%5,%6,%7}, {%8,%9}, {%0,%1,%2,%3};"
        : "+f"(c0), "+f"(c1), "+f"(c2), "+f"(c3)
        : "r"(a0), "r"(a1), "r"(a2), "r"(a3), "r"(b0), "r"(b1));
}
__device__ __forceinline__ void mbar_wait(uint32_t mbar, uint32_t parity) {
    uint32_t done;
    asm volatile(
        "{\n\t.reg .pred p;\n\t"
        "mbarrier.try_wait.parity.acquire.cta.shared::cta.b64 p, [%1], %2;\n\t"
        "selp.b32 %0, 1, 0, p;\n\t}"
        : "=r"(done) : "r"(mbar), "r"(parity) : "memory");
    if (!done) {
        asm volatile(
            "{\n\t.reg .pred P1;\n\t"
            "WL_%=:\n\t"
            "mbarrier.try_wait.parity.acquire.cta.shared::cta.b64 P1, [%0], %1, 0x989680;\n\t"
            "@P1 bra.uni WD_%=;\n\t"
            "bra.uni WL_%=;\n\t"
            "WD_%=:\n\t}"
            :: "r"(mbar), "r"(parity) : "memory");
    }
}

// ---------------------------------------------------------------------------
// fp16 mma.sync GEMM: C[M,N] = A[M,K] * Bt[N,K]^T, single phase.
// Block tile 128x128x64, 8 warps (2x4), warp tile 64x32, 3-stage cp.async,
// DECOUPLED mbarrier pipeline (no block-wide barrier in the mainloop).
// FUSE=true: store o = acc + bias[col] + resid[row,col] as fp16 (GEMM2 path).
// FUSE=false: store raw acc as fp16 (GEMM1 / C1 path).
// ---------------------------------------------------------------------------
#define GS 3
#define PITCH 144
#define ATILE_B (128 * PITCH)          // 18432
#define STAGE_B (2 * ATILE_B)          // 36864
#define GSMEM_TOTAL (GS * STAGE_B + 64)

template <bool FUSE>
__global__ __launch_bounds__(256, 2)
void mma_gemm_kernel(const __half* __restrict__ A,
                     const __half* __restrict__ B,
                     __half* __restrict__ C, int M, int K, int N,
                     const float* __restrict__ bias,
                     const float* __restrict__ resid)
{
    extern __shared__ char smem[];
    const uint32_t sbase = smem_u32(smem);
    const uint32_t mb    = sbase + GS * STAGE_B;   // full[3] @ +0, empty[3] @ +32
    const int tid  = threadIdx.x;
    const int wid  = tid >> 5;
    const int lane = tid & 31;
    const int wm   = wid & 1;          // 0..1
    const int wn   = wid >> 1;         // 0..3
    const int g    = lane >> 2;        // 0..7
    const int tig  = lane & 3;         // 0..3

    const int nbase = blockIdx.x * 128;
    const int mbase = blockIdx.y * 128;

    const int TOT = K >> 6;            // K tiles of 64

    if (tid == 0) {
        #pragma unroll
        for (int s = 0; s < GS; s++) {
            asm volatile("mbarrier.init.shared.b64 [%0], %1;"
                         :: "r"(mb + s * 8), "r"(256u) : "memory");
            asm volatile("mbarrier.init.shared.b64 [%0], %1;"
                         :: "r"(mb + 32 + s * 8), "r"(256u) : "memory");
        }
    }
    __syncthreads();

    // ldmatrix per-lane base offsets (within a stage's A / B region)
    const uint32_t aoff = (uint32_t)(wm * 64 + (lane & 7) + ((lane >> 3) & 1) * 8) * PITCH
                        + (uint32_t)(lane >> 4) * 16;
    const uint32_t boff = (uint32_t)(wn * 32 + ((lane >> 4) & 1) * 8 + (lane & 7)) * PITCH
                        + (uint32_t)((lane >> 3) & 1) * 16;

    // producer state: stage pst, round pk, K offset pkk
    int pst = 0, pk = 0;
    uint32_t pkk = 0;
    auto produce = [&]() {
        if (pk > 0) mbar_wait(mb + 32 + pst * 8, (uint32_t)((pk & 1) ^ 1));  // empty
        const uint32_t sA = sbase + pst * STAGE_B;
        const uint32_t sB = sA + ATILE_B;
        #pragma unroll
        for (int h = 0; h < 4; h++) {
            int c  = tid + h * 256;
            int r  = c >> 3;
            int cc = c & 7;
            int grow = mbase + r;
            uint32_t ok = (grow < M) ? 16u : 0u;
            const void* srcA = A + ((size_t)(ok ? grow : 0) * K + pkk + cc * 8);
            cp_async16(sA + r * PITCH + cc * 16, srcA, ok);
            const void* srcB = B + ((size_t)(nbase + r) * K + pkk + cc * 8);
            cp_async16(sB + r * PITCH + cc * 16, srcB, 16u);
        }
        asm volatile("cp.async.mbarrier.arrive.noinc.shared.b64 [%0];"
                     :: "r"(mb + pst * 8) : "memory");                        // full
        pkk += 64;
        if (++pst == GS) { pst = 0; pk++; }
    };

    float acc[4][4][4];
    #pragma unroll
    for (int mt = 0; mt < 4; mt++)
        #pragma unroll
        for (int nt = 0; nt < 4; nt++)
            #pragma unroll
            for (int e = 0; e < 4; e++)
                acc[mt][nt][e] = 0.f;

    // prologue: prefetch 2 stages
    produce(); produce();

    int cst = 0, ck = 0;
    for (int it = 0; it < TOT; it++) {
        mbar_wait(mb + cst * 8, (uint32_t)(ck & 1));    // full[cst], acquire

        const uint32_t sA = sbase + cst * STAGE_B;
        const uint32_t sB = sA + ATILE_B;

        auto do_chunk = [&](int kk) {
            uint32_t bf[4][2];
            #pragma unroll
            for (int np = 0; np < 2; np++) {
                ldsm_x4(bf[2 * np][0], bf[2 * np][1],
                        bf[2 * np + 1][0], bf[2 * np + 1][1],
                        sB + boff + (uint32_t)np * (16 * PITCH) + (uint32_t)kk * 2);
            }
            #pragma unroll
            for (int mt = 0; mt < 4; mt++) {
                uint32_t a0, a1, a2, a3;
                ldsm_x4(a0, a1, a2, a3,
                        sA + aoff + (uint32_t)mt * (16 * PITCH) + (uint32_t)kk * 2);
                #pragma unroll
                for (int nt = 0; nt < 4; nt++)
                    mma_f16(acc[mt][nt][0], acc[mt][nt][1],
                            acc[mt][nt][2], acc[mt][nt][3],
                            a0, a1, a2, a3, bf[nt][0], bf[nt][1]);
            }
        };

        do_chunk(0);
        if (it + 2 < TOT) produce();   // fills stage (it+2)%3, waits empty of it-1
        do_chunk(16);
        do_chunk(32);
        do_chunk(48);

        asm volatile("mbarrier.arrive.shared.b64 _, [%0];"
                     :: "r"(mb + 32 + cst * 8) : "memory");   // empty[cst], release
        if (++cst == GS) { cst = 0; ck++; }
    }

    // store fp16; FUSE path adds bias[col] + resid[row, col] first
    #pragma unroll
    for (int mt = 0; mt < 4; mt++) {
        int row = mbase + wm * 64 + mt * 16 + g;
        #pragma unroll
        for (int nt = 0; nt < 4; nt++) {
            int col = nbase + wn * 32 + nt * 8 + tig * 2;
            if (row < M) {
                float v0 = acc[mt][nt][0], v1 = acc[mt][nt][1];
                if constexpr (FUSE) {
                    float2 bi = *(const float2*)(bias + col);
                    float2 xi = *(const float2*)(resid + (size_t)row * N + col);
                    v0 += bi.x + xi.x;  v1 += bi.y + xi.y;
                }
                *(__half2*)(C + (size_t)row * N + col) = __floats2half2_rn(v0, v1);
            }
            if (row + 8 < M) {
                float v2 = acc[mt][nt][2], v3 = acc[mt][nt][3];
                if constexpr (FUSE) {
                    float2 bi = *(const float2*)(bias + col);
                    float2 xi = *(const float2*)(resid + (size_t)(row + 8) * N + col);
                    v2 += bi.x + xi.x;  v3 += bi.y + xi.y;
                }
                *(__half2*)(C + (size_t)(row + 8) * N + col) = __floats2half2_rn(v2, v3);
            }
        }
    }
}

// ---------------------------------------------------------------------------
// E0: build XT1 (fp16) from inputs/lf1 (p = s*2049+j; j==0 -> cache row)
// ---------------------------------------------------------------------------
__global__ void build_xt1_kernel(const float* __restrict__ inputs,
                                 const float* __restrict__ lf1)
{
    int p = blockIdx.x;
    int s = p / (LSEQ + 1);
    int j = p - s * (LSEQ + 1);
    const float* src = (j == 0)
        ? (lf1 + (size_t)s * DDIM)
        : (inputs + ((size_t)s * LSEQ + (j - 1)) * DDIM);
    __half* dh = g_XT1 + (size_t)p * DDIM;
    int base = threadIdx.x * 8;
    #pragma unroll
    for (int v = 0; v < 2; v++) {
        float4 x = *(const float4*)(src + base + v * 4);
        *(__half2*)(dh + base + v * 4)     = __floats2half2_rn(x.x, x.y);
        *(__half2*)(dh + base + v * 4 + 2) = __floats2half2_rn(x.z, x.w);
    }
}

// ---------------------------------------------------------------------------
// E1: build Z[t] = [ XT2[p] , XT2[p+1] ]  (p = s*2049 + j for token t=(s,j))
//   XT2[q] = (q at j==0) ? lf2[s] : C1[q-1,:1024] + C1[q,1024:] + b1
// C1 fp16: half2 loads, float math, half2 stores.
// ---------------------------------------------------------------------------
__global__ void build_z_kernel(const float* __restrict__ lf2,
                               const float* __restrict__ b1)
{
    int t = blockIdx.x;
    int s = t >> 11;
    int j = t & 2047;
    size_t p = (size_t)s * (LSEQ + 1) + j;

    __half* z = g_Z + (size_t)t * K2;
    int base = threadIdx.x * 4;
    float4 bi = *(const float4*)(b1 + base);

    // half 1: XT2[p]
    float r1x, r1y, r1z, r1w;
    if (j == 0) {
        float4 r = *(const float4*)(lf2 + (size_t)s * H1 + base);
        r1x = r.x; r1y = r.y; r1z = r.z; r1w = r.w;
    } else {
        float2 a01 = __half22float2(*(const __half2*)(g_C1 + (p - 1) * DDIM + base));
        float2 a23 = __half22float2(*(const __half2*)(g_C1 + (p - 1) * DDIM + base + 2));
        float2 b01 = __half22float2(*(const __half2*)(g_C1 + p * DDIM + H1 + base));
        float2 b23 = __half22float2(*(const __half2*)(g_C1 + p * DDIM + H1 + base + 2));
        r1x = a01.x + b01.x + bi.x;  r1y = a01.y + b01.y + bi.y;
        r1z = a23.x + b23.x + bi.z;  r1w = a23.y + b23.y + bi.w;
    }
    // half 2: XT2[p+1] (always the conv path; p+1 has j>=1)
    float2 c01 = __half22float2(*(const __half2*)(g_C1 + p * DDIM + base));
    float2 c23 = __half22float2(*(const __half2*)(g_C1 + p * DDIM + base + 2));
    float2 d01 = __half22float2(*(const __half2*)(g_C1 + (p + 1) * DDIM + H1 + base));
    float2 d23 = __half22float2(*(const __half2*)(g_C1 + (p + 1) * DDIM + H1 + base + 2));
    float r2x = c01.x + d01.x + bi.x,  r2y = c01.y + d01.y + bi.y;
    float r2z = c23.x + d23.x + bi.z,  r2w = c23.y + d23.y + bi.w;

    *(__half2*)(z + base)          = __floats2half2_rn(r1x, r1y);
    *(__half2*)(z + base + 2)      = __floats2half2_rn(r1z, r1w);
    *(__half2*)(z + H1 + base)     = __floats2half2_rn(r2x, r2y);
    *(__half2*)(z + H1 + base + 2) = __floats2half2_rn(r2z, r2w);
}

// ---------------------------------------------------------------------------
// Transpose W1 -> fp16: g_W1t[c][r] = fp16(W[r][c]);  W is [R, Cc]
// ---------------------------------------------------------------------------
__global__ void transpose_w1_kernel(const float* __restrict__ W, int R, int Cc)
{
    __shared__ float t[32][33];
    int tx = threadIdx.x, ty = threadIdx.y;           // 32 x 8
    int r0 = blockIdx.y * 32, c0 = blockIdx.x * 32;
    #pragma unroll
    for (int k = 0; k < 4; k++)
        t[ty + 8 * k][tx] = W[(size_t)(r0 + ty + 8 * k) * Cc + c0 + tx];
    __syncthreads();
    #pragma unroll
    for (int k = 0; k < 4; k++) {
        int c = c0 + ty + 8 * k;
        int r = r0 + tx;
        g_W1t[(size_t)c * R + r] = __float2half_rn(t[tx][ty + 8 * k]);
    }
}

// ---------------------------------------------------------------------------
// Transpose W2' -> fp16: g_W2p[n][k'] (2048x2048), where
//   k' < 1024: W2[k'][n] ; k' >= 1024: W2[k'-1024][2048+n]   (W2 is [1024][4096])
// ---------------------------------------------------------------------------
__global__ void transpose_w2p_kernel(const float* __restrict__ W2)
{
    __shared__ float t[32][33];
    int tx = threadIdx.x, ty = threadIdx.y;           // 32 x 8
    int k0 = blockIdx.y * 32, n0 = blockIdx.x * 32;
    int half = k0 >> 10;
    int kr0  = k0 & 1023;
    #pragma unroll
    for (int u = 0; u < 4; u++)
        t[ty + 8 * u][tx] = W2[(size_t)(kr0 + ty + 8 * u) * 4096 + half * 2048 + n0 + tx];
    __syncthreads();
    #pragma unroll
    for (int u = 0; u < 4; u++) {
        int n = n0 + ty + 8 * u;
        int k = k0 + tx;
        g_W2p[(size_t)n * K2 + k] = __float2half_rn(t[tx][ty + 8 * u]);
    }
}

// ---------------------------------------------------------------------------
// E2: epilogue, slim: out[t] = o3[t] * rsqrt(mean(o3^2)+eps) * lnw
// (bias + residual already folded into GEMM2's fused store; o3 is fp16)
// ---------------------------------------------------------------------------
__global__ void epilogue_kernel(const float* __restrict__ lnw,
                                float* __restrict__ out)
{
    int t = blockIdx.x;
    const __half* rowO = g_O3 + (size_t)t * N2P;

    int base = threadIdx.x * 8;
    float o[8];
    float ss = 0.f;
    #pragma unroll
    for (int v = 0; v < 4; v++) {
        float2 h = __half22float2(*(const __half2*)(rowO + base + v * 2));
        o[v * 2 + 0] = h.x;
        o[v * 2 + 1] = h.y;
        ss += h.x * h.x + h.y * h.y;
    }

    __shared__ float red[8];
    #pragma unroll
    for (int off = 16; off > 0; off >>= 1)
        ss += __shfl_xor_sync(0xFFFFFFFFu, ss, off);
    int lane = threadIdx.x & 31;
    int wid  = threadIdx.x >> 5;
    if (lane == 0) red[wid] = ss;
    __syncthreads();
    float total = 0.f;
    #pragma unroll
    for (int w = 0; w < 8; w++) total += red[w];

    float scale = rsqrtf(total * (1.0f / DDIM) + 1e-6f);

    float* op = out + (size_t)t * DDIM;
    #pragma unroll
    for (int v = 0; v < 2; v++) {
        float4 lw = *(const float4*)(lnw + base + v * 4);
        float4 r;
        r.x = o[v * 4 + 0] * scale * lw.x;
        r.y = o[v * 4 + 1] * scale * lw.y;
        r.z = o[v * 4 + 2] * scale * lw.z;
        r.w = o[v * 4 + 3] * scale * lw.w;
        *(float4*)(op + base + v * 4) = r;
    }
}

// ---------------------------------------------------------------------------
// kernel_launch
// ---------------------------------------------------------------------------
extern "C" void kernel_launch(void* const* d_in, const int* in_sizes, int n_in,
                              void* d_out, int out_size)
{
    const float* inputs = (const float*)d_in[0];
    const float* lf1    = (const float*)d_in[7];
    const float* lf2    = (const float*)d_in[8];
    const float* W1     = (const float*)d_in[9];
    const float* W2     = (const float*)d_in[10];
    const float* b1     = (const float*)d_in[11];
    const float* b2     = (const float*)d_in[12];
    const float* lnw    = (const float*)d_in[13];
    float* out          = (float*)d_out;

    static __half *pXT1, *pZ, *pW1, *pW2, *pC1, *pO3;
    static bool init_done = false;
    if (!init_done) {
        cudaGetSymbolAddress((void**)&pXT1, g_XT1);
        cudaGetSymbolAddress((void**)&pZ,   g_Z);
        cudaGetSymbolAddress((void**)&pW1,  g_W1t);
        cudaGetSymbolAddress((void**)&pW2,  g_W2p);
        cudaGetSymbolAddress((void**)&pC1,  g_C1);
        cudaGetSymbolAddress((void**)&pO3,  g_O3);
        cudaFuncSetAttribute(mma_gemm_kernel<false>,
                             cudaFuncAttributeMaxDynamicSharedMemorySize, GSMEM_TOTAL);
        cudaFuncSetAttribute(mma_gemm_kernel<true>,
                             cudaFuncAttributeMaxDynamicSharedMemorySize, GSMEM_TOTAL);
        init_done = true;
    }

    // E0: XT1 (fp16)
    build_xt1_kernel<<<ROWS, 256>>>(inputs, lf1);

    // Weight transposes (single fp16)
    transpose_w1_kernel<<<dim3(DDIM / 32, DDIM / 32), dim3(32, 8)>>>(W1, DDIM, DDIM);
    transpose_w2p_kernel<<<dim3(N2P / 32, K2 / 32), dim3(32, 8)>>>(W2);

    // G1: C1 = XT1 @ W1   [16392,2048]x[2048,2048], fp16 output, no fusion
    {
        dim3 grid(DDIM / 128, (ROWS + 127) / 128);   // 16 x 129
        mma_gemm_kernel<false><<<grid, 256, GSMEM_TOTAL>>>(pXT1, pW1, pC1,
                                                           ROWS, DDIM, DDIM,
                                                           nullptr, nullptr);
    }

    // E1: build Z from C1 (conv-2 shift folded into GEMM2 operand)
    build_z_kernel<<<TOK, 256>>>(lf2, b1);

    // G2: o3 = Z @ W2' + b2 + inputs   [16384,2048]x[2048,2048], fused fp16 store
    {
        dim3 grid(N2P / 128, TOK / 128);             // 16 x 128
        mma_gemm_kernel<true><<<grid, 256, GSMEM_TOTAL>>>(pZ, pW2, pO3,
                                                          TOK, K2, N2P,
                                                          b2, inputs);
    }

    // E2: slim epilogue (RMSNorm only)
    epilogue_kernel<<<TOK, 256>>>(lnw, out);
}